// round 14
// baseline (speedup 1.0000x reference)
#include <cuda_runtime.h>
#include <cstdint>
#include <math.h>

// ---------------------------------------------------------------------------
// PolicyGradientLoss: out = mean( nll(w,a) * (D - mean D) )
//   D[t] = sum_{k>=t} gamma^{k-t} r[k]       (reverse affine scan)
//   nll[t] = logsumexp(w[t,:]) - w[t, a[t]]
// Identity: mean(nll*(D-mD)) = (S_pd - S_d*S_n/T)/T
// ep_as is int32 on device.
//
// R14 (base = R12, revert R13): 16 tiles x 128 rows, NBUF=3 depth-2 cp.async
// ring (35KB smem -> 6 blocks/SM, occ 75%), tile computed by parity-half of
// the block. k_agg is warp-granular (256-row warp-chunks, no block scan);
// fused scan uses per-warp cin with warp-only suffix scan.
// ---------------------------------------------------------------------------

#define GAMMA 0.99f
#define BT 256                          // threads per block (8 warps)
#define FPT 8                           // rows per thread in scan
#define FCHUNK (BT * FPT)               // 2048 rows per block
#define MAXT (1 << 22)
#define WCH 256                         // rows per warp-chunk (scan granularity)
#define MAXW (MAXT / WCH)               // 16384
#define AH 9                            // float2 per row (A = 18)
#define ROWB 72                         // bytes per row
#define TROWS 128                       // rows per tile
#define TBYTES (TROWS * ROWB)           // 9216 B per tile
#define NGR (TBYTES / 16)               // 576 granules per tile
#define NTILE (FCHUNK / TROWS)          // 16 tiles per chunk
#define NBUF 3
#define DYNBYTES (NBUF * TBYTES + FCHUNK * 4)   // 27648 + 8192 = 35840

static __device__ float  g_cg[MAXW];
static __device__ float  g_cs[MAXW];
static __device__ float  g_cin[MAXW];
static __device__ double g_acc[3];      // [0]=sum d, [1]=sum nll, [2]=sum nll*d
static __device__ unsigned int g_ctr;   // fused finish ticket
static __device__ unsigned int g_ctr2;  // agg finish ticket

__device__ __forceinline__ float gamma8() {
    float g2 = GAMMA * GAMMA; float g4 = g2 * g2; return g4 * g4;
}

__device__ __forceinline__ void cp16(unsigned int saddr, const void* gptr) {
    asm volatile("cp.async.cg.shared.global [%0], [%1], 16;"
                 :: "r"(saddr), "l"(gptr) : "memory");
}
__device__ __forceinline__ void cp_commit() {
    asm volatile("cp.async.commit_group;" ::: "memory");
}
template <int N>
__device__ __forceinline__ void cp_wait() {
    asm volatile("cp.async.wait_group %0;" :: "n"(N) : "memory");
}

// Issue one 128-row tile copy with all BT threads (576 granules)
__device__ __forceinline__ void issue_tile(unsigned int dst, const char* src, int tid) {
    #pragma unroll
    for (int j = 0; j < 3; j++) {
        int i = tid + j * BT;
        if (i < NGR) cp16(dst + i * 16, src + (long long)i * 16);
    }
    cp_commit();
}

__device__ __forceinline__ void load8(const float* __restrict__ r, long long base,
                                      long long T, float rv[FPT]) {
    if (base + FPT <= T) {
        const float4* p = reinterpret_cast<const float4*>(r + base);
        float4 v0 = p[0], v1 = p[1];
        rv[0]=v0.x; rv[1]=v0.y; rv[2]=v0.z; rv[3]=v0.w;
        rv[4]=v1.x; rv[5]=v1.y; rv[6]=v1.z; rv[7]=v1.w;
    } else {
        #pragma unroll
        for (int j = 0; j < FPT; j++)
            rv[j] = (base + j < T) ? r[base + j] : 0.0f;
    }
}

// Warp inclusive suffix scan of affine (g,s): lane i -> aggregate [i..31].
__device__ __forceinline__ void warp_suffix_incl(float& g, float& s) {
    int lane = threadIdx.x & 31;
    #pragma unroll
    for (int off = 1; off < 32; off <<= 1) {
        float g2 = __shfl_down_sync(0xffffffffu, g, off);
        float s2 = __shfl_down_sync(0xffffffffu, s, off);
        if (lane + off < 32) { s = s + g * s2; g = g * g2; }
    }
}

// Warp-only: carry entering this lane's segment given warp-incoming carry cin.
__device__ __forceinline__ float lane_carry(float gseg, float sseg, float cin) {
    int lane = threadIdx.x & 31;
    float g = gseg, s = sseg;
    warp_suffix_incl(g, s);
    float ge = __shfl_down_sync(0xffffffffu, g, 1);
    float se = __shfl_down_sync(0xffffffffu, s, 1);
    if (lane == 31) { ge = 1.0f; se = 0.0f; }
    return se + ge * cin;
}

// Block-level carry (used only in k_agg tail). Leaves shg/shs = warp aggregates.
__device__ __forceinline__ float thread_carry(float gseg, float sseg, float cin,
                                              float* shg, float* shs) {
    int lane = threadIdx.x & 31, wid = threadIdx.x >> 5;
    int nw = blockDim.x >> 5;
    float g = gseg, s = sseg;
    warp_suffix_incl(g, s);
    float ge = __shfl_down_sync(0xffffffffu, g, 1);
    float se = __shfl_down_sync(0xffffffffu, s, 1);
    if (lane == 31) { ge = 1.0f; se = 0.0f; }
    if (lane == 0) { shg[wid] = g; shs[wid] = s; }
    __syncthreads();
    float gw = 1.0f, sw = 0.0f;
    for (int wv = wid + 1; wv < nw; wv++) { sw = sw + gw * shs[wv]; gw = gw * shg[wv]; }
    return se + ge * (sw + gw * cin);
}

// Float warp reduce -> per-warp double partial -> warp0 double reduce -> atomics
__device__ __forceinline__ void block_reduce3f(float a, float b, float c) {
    #pragma unroll
    for (int o = 16; o > 0; o >>= 1) {
        a += __shfl_down_sync(0xffffffffu, a, o);
        b += __shfl_down_sync(0xffffffffu, b, o);
        c += __shfl_down_sync(0xffffffffu, c, o);
    }
    __shared__ double sa[8], sb[8], sc[8];
    int lane = threadIdx.x & 31, wid = threadIdx.x >> 5;
    if (lane == 0) { sa[wid] = (double)a; sb[wid] = (double)b; sc[wid] = (double)c; }
    __syncthreads();
    if (wid == 0) {
        int nw = blockDim.x >> 5;
        double da = (lane < nw) ? sa[lane] : 0.0;
        double db = (lane < nw) ? sb[lane] : 0.0;
        double dc = (lane < nw) ? sc[lane] : 0.0;
        #pragma unroll
        for (int o = 4; o > 0; o >>= 1) {
            da += __shfl_down_sync(0xffffffffu, da, o);
            db += __shfl_down_sync(0xffffffffu, db, o);
            dc += __shfl_down_sync(0xffffffffu, dc, o);
        }
        if (lane == 0) {
            atomicAdd(&g_acc[0], da);
            atomicAdd(&g_acc[1], db);
            atomicAdd(&g_acc[2], dc);
        }
    }
}

// ---------------------------------------------------------------------------
// Kernel 1: per-warp-chunk (256-row) aggregates, no block scan. Last-finished
// block runs the suffix scan over warp-chunks and resets accumulators/tickets.
// ---------------------------------------------------------------------------
__global__ void __launch_bounds__(BT) k_agg(const float* __restrict__ r, long long T) {
    __shared__ float shg[BT / 32], shs[BT / 32];
    __shared__ int is_last;
    int tid = threadIdx.x;
    int lane = tid & 31, wid = tid >> 5;
    long long W = (long long)blockIdx.x * 8 + wid;          // warp-chunk id
    long long base = W * WCH + (long long)lane * FPT;
    float rv[FPT];
    load8(r, base, T, rv);
    int cnt = (int)max(0LL, min((long long)FPT, T - base));
    float carry = 0.0f;
    #pragma unroll
    for (int j = FPT - 1; j >= 0; --j) carry = carry * GAMMA + rv[j];
    float g = (cnt == FPT) ? gamma8() : __powf(GAMMA, (float)cnt);
    float s = carry;
    warp_suffix_incl(g, s);
    if (lane == 0) { g_cg[W] = g; g_cs[W] = s; }
    __syncthreads();
    if (tid == 0) {
        __threadfence();
        is_last = (atomicAdd(&g_ctr2, 1u) == gridDim.x - 1u) ? 1 : 0;
    }
    __syncthreads();
    if (!is_last) return;

    // --- last block: suffix scan over all warp-chunks + housekeeping ---
    __threadfence();   // acquire other blocks' g_cg/g_cs
    if (tid == 0) { g_acc[0] = 0.0; g_acc[1] = 0.0; g_acc[2] = 0.0;
                    g_ctr = 0u; g_ctr2 = 0u; }
    __syncthreads();
    int NW = gridDim.x * 8;
    int kc = (NW + BT - 1) / BT;
    int lo = tid * kc;
    int hi = min(lo + kc, NW);
    float cg = 1.0f, cs = 0.0f;
    for (int c = lo; c < hi; c++) { cs = cs + cg * g_cs[c]; cg = cg * g_cg[c]; }
    float scarry = thread_carry(cg, cs, 0.0f, shg, shs);
    for (int c = hi - 1; c >= lo; --c) {
        g_cin[c] = scarry;
        scarry = g_cs[c] + g_cg[c] * scarry;
    }
}

// ---------------------------------------------------------------------------
// Kernel 2 (fused): warp-scan replay + depth-2 cp.async ring over 128-row
// tiles (parity-half compute). Last-block ticket computes the final scalar.
// A == 18 specialization.
// ---------------------------------------------------------------------------
__global__ void __launch_bounds__(BT) k_fused18(const float* __restrict__ w,
                                                const float* __restrict__ r,
                                                const int* __restrict__ as,
                                                long long T, float* out) {
    extern __shared__ __align__(16) char dyns[];
    char*  wbuf = dyns;                                            // NBUF*TBYTES
    float* sd   = reinterpret_cast<float*>(dyns + NBUF * TBYTES);  // FCHUNK
    int tid = threadIdx.x;
    int lane = tid & 31, wid = tid >> 5;
    long long cbase = (long long)blockIdx.x * FCHUNK;
    bool full = (cbase + FCHUNK <= T);
    const char* wbase = reinterpret_cast<const char*>(w) + cbase * ROWB;

    unsigned int sb[NBUF];
    #pragma unroll
    for (int b = 0; b < NBUF; b++)
        sb[b] = (unsigned int)__cvta_generic_to_shared(wbuf + b * TBYTES);

    // prologue: issue tiles 0, 1
    if (full) {
        issue_tile(sb[0], wbase, tid);
        issue_tile(sb[1], wbase + TBYTES, tid);
    }

    // --- scan replay (warp-local, no block barriers) ---
    long long base = cbase + (long long)tid * FPT;
    float rv[FPT];
    load8(r, base, T, rv);
    int cnt = (int)max(0LL, min((long long)FPT, T - base));
    float carry = 0.0f;
    #pragma unroll
    for (int j = FPT - 1; j >= 0; --j) carry = carry * GAMMA + rv[j];
    float gseg = (cnt == FPT) ? gamma8() : __powf(GAMMA, (float)cnt);
    float cin = g_cin[(long long)blockIdx.x * 8 + wid];
    float tc = lane_carry(gseg, carry, cin);

    float dsum = 0.0f;
    {
        float c2 = tc;
        if (cnt == FPT) {
            float dloc[FPT];
            #pragma unroll
            for (int j = FPT - 1; j >= 0; --j) { c2 = c2 * GAMMA + rv[j]; dloc[j] = c2; }
            #pragma unroll
            for (int j = 0; j < FPT; j++) { sd[tid * FPT + j] = dloc[j]; dsum += dloc[j]; }
        } else {
            for (int j = FPT - 1; j >= 0; --j) {
                if (j < cnt) { c2 = c2 * GAMMA + rv[j]; sd[tid * FPT + j] = c2; dsum += c2; }
                else sd[tid * FPT + j] = 0.0f;
            }
        }
    }
    __syncthreads();   // sd visible block-wide

    float pn = 0.0f, pp = 0.0f;

    if (full) {
        int half = tid >> 7;           // 0 or 1
        int rl = tid & 127;            // row within tile
        #pragma unroll
        for (int t = 0; t < NTILE; t++) {
            if (t + 1 < NTILE) cp_wait<1>(); else cp_wait<0>();
            __syncthreads();           // tile t's buffer visible; t-1 reads done

            if (t + 2 < NTILE)
                issue_tile(sb[(t + 2) % NBUF], wbase + (long long)(t + 2) * TBYTES, tid);

            if (half == (t & 1)) {
                int rloc = t * TROWS + rl;
                long long tg = cbase + rloc;
                int ai = as[tg];
                const float2* myrow = reinterpret_cast<const float2*>(
                    wbuf + (t % NBUF) * TBYTES) + rl * AH;
                float s0 = 0.0f, s1 = 0.0f;
                #pragma unroll
                for (int i = 0; i < AH; i++) {
                    float2 v = myrow[i];
                    s0 += __expf(v.x);
                    s1 += __expf(v.y);
                }
                float2 va = myrow[ai >> 1];
                float wa = (ai & 1) ? va.y : va.x;
                float nll = __logf(s0 + s1) - wa;
                pn += nll;
                pp += nll * sd[rloc];
            }
        }
    } else {
        // partial last chunk: direct loads (at most one block)
        for (int t = 0; t < NTILE; t++) {
            if ((tid >> 7) == (t & 1)) {
                long long tg = cbase + t * TROWS + (tid & 127);
                if (tg < T) {
                    const float* row = w + (size_t)tg * (AH * 2);
                    const float2* p2 = reinterpret_cast<const float2*>(row);
                    float s = 0.0f;
                    #pragma unroll
                    for (int i = 0; i < AH; i++) {
                        float2 v = __ldg(p2 + i);
                        s += __expf(v.x) + __expf(v.y);
                    }
                    int ai = as[tg];
                    float nll = __logf(s) - __ldg(row + ai);
                    pn += nll;
                    pp += nll * sd[t * TROWS + (tid & 127)];
                }
            }
        }
    }

    block_reduce3f(dsum, pn, pp);

    if (tid == 0) {
        __threadfence();
        if (atomicAdd(&g_ctr, 1u) == gridDim.x - 1) {
            __threadfence();
            double Td = (double)T;
            double ds = g_acc[0], ns = g_acc[1], ps = g_acc[2];
            out[0] = (float)((ps - ds * ns / Td) / Td);
            g_ctr = 0u;
        }
    }
}

// Generic-A fallback (direct loads, warp-scan, float accumulators)
__global__ void __launch_bounds__(BT) k_fused_gen(const float* __restrict__ w,
                                                  const float* __restrict__ r,
                                                  const int* __restrict__ as,
                                                  long long T, int A, float* out) {
    extern __shared__ __align__(16) char dyns[];
    float* sd = reinterpret_cast<float*>(dyns + NBUF * TBYTES);
    int tid = threadIdx.x;
    int wid = tid >> 5;
    long long cbase = (long long)blockIdx.x * FCHUNK;
    long long base = cbase + (long long)tid * FPT;

    float rv[FPT];
    load8(r, base, T, rv);
    int cnt = (int)max(0LL, min((long long)FPT, T - base));
    float carry = 0.0f;
    #pragma unroll
    for (int j = FPT - 1; j >= 0; --j) carry = carry * GAMMA + rv[j];
    float gseg = (cnt == FPT) ? gamma8() : __powf(GAMMA, (float)cnt);
    float tc = lane_carry(gseg, carry, g_cin[(long long)blockIdx.x * 8 + wid]);

    float dsum = 0.0f;
    {
        float c2 = tc;
        for (int j = FPT - 1; j >= 0; --j) {
            if (j < cnt) { c2 = c2 * GAMMA + rv[j]; sd[tid * FPT + j] = c2; dsum += c2; }
            else sd[tid * FPT + j] = 0.0f;
        }
    }
    __syncthreads();

    float pn = 0.0f, pp = 0.0f;
    for (int j = 0; j < FPT; j++) {
        long long t = cbase + (long long)j * BT + tid;
        if (t < T) {
            const float* row = w + (size_t)t * A;
            float m = __ldg(row);
            for (int i = 1; i < A; i++) m = fmaxf(m, __ldg(row + i));
            float s = 0.0f;
            for (int i = 0; i < A; i++) s += __expf(__ldg(row + i) - m);
            int ai = as[t];
            float nll = m + __logf(s) - __ldg(row + ai);
            pn += nll;
            pp += nll * sd[j * BT + tid];
        }
    }
    __syncthreads();
    block_reduce3f(dsum, pn, pp);

    if (tid == 0) {
        __threadfence();
        if (atomicAdd(&g_ctr, 1u) == gridDim.x - 1) {
            __threadfence();
            double Td = (double)T;
            double ds = g_acc[0], ns = g_acc[1], ps = g_acc[2];
            out[0] = (float)((ps - ds * ns / Td) / Td);
            g_ctr = 0u;
        }
    }
}

extern "C" void kernel_launch(void* const* d_in, const int* in_sizes, int n_in,
                              void* d_out, int out_size) {
    const float* w  = (const float*)d_in[0];   // [T, A]
    const float* r  = (const float*)d_in[1];   // [T]
    const int*   as = (const int*)d_in[2];     // [T] int32
    long long T = (long long)in_sizes[1];
    int A = (int)((long long)in_sizes[0] / T);
    long long NCll = (T + FCHUNK - 1) / FCHUNK;
    if (NCll > MAXT / FCHUNK) NCll = MAXT / FCHUNK;
    int NC = (int)NCll;

    static int attr_done = 0;
    if (!attr_done) {
        cudaFuncSetAttribute(k_fused18, cudaFuncAttributeMaxDynamicSharedMemorySize, DYNBYTES);
        cudaFuncSetAttribute(k_fused_gen, cudaFuncAttributeMaxDynamicSharedMemorySize, DYNBYTES);
        attr_done = 1;
    }

    k_agg<<<NC, BT>>>(r, T);
    if (A == 18) k_fused18<<<NC, BT, DYNBYTES>>>(w, r, as, T, (float*)d_out);
    else         k_fused_gen<<<NC, BT, DYNBYTES>>>(w, r, as, T, A, (float*)d_out);
}

// round 15
// speedup vs baseline: 1.1197x; 1.1197x over previous
#include <cuda_runtime.h>
#include <cstdint>
#include <math.h>

// ---------------------------------------------------------------------------
// PolicyGradientLoss: out = mean( nll(w,a) * (D - mean D) )
//   D[t] = sum_{k>=t} gamma^{k-t} r[k]       (reverse affine scan)
//   nll[t] = logsumexp(w[t,:]) - w[t, a[t]]
// Identity: mean(nll*(D-mD)) = (S_pd - S_d*S_n/T)/T
// ep_as is int32 on device.
//
// R15: single kernel. R12's proven mainloop (256-row tiles, NBUF=2 ping-pong,
// one barrier per tile) + decoupled look-back for the scan carry (chunk id
// reversed vs blockIdx so dependencies point at earlier-scheduled blocks).
// Last-block ticket finalizes and resets flags for graph replay.
// ---------------------------------------------------------------------------

#define GAMMA 0.99f
#define BT 256                          // threads per block (8 warps)
#define FPT 8                           // rows per thread in scan
#define FCHUNK (BT * FPT)               // 2048 rows per block
#define MAXT (1 << 22)
#define MAXC (MAXT / FCHUNK)            // 2048
#define AH 9                            // float2 per row (A = 18)
#define ROWB 72                         // bytes per row
#define TBYTES (BT * ROWB)              // 18432 B per 256-row tile
#define NG16 (TBYTES / 16)              // 1152 granules per tile
#define NBUF 2
#define NTILE (FCHUNK / BT)             // 8 tiles per chunk
#define DYNBYTES (NBUF * TBYTES + FCHUNK * 4)   // 45056

// look-back state (zero-initialized at load; last block re-zeroes per launch)
static __device__ float g_pg[MAXC];     // chunk aggregate gain
static __device__ float g_ps[MAXC];     // chunk aggregate sum
static __device__ float g_pi[MAXC];     // chunk inclusive suffix value
static __device__ int   g_st[MAXC];     // 0 empty / 1 agg / 2 inclusive
static __device__ double g_acc[3];      // [0]=sum d, [1]=sum nll, [2]=sum nll*d
static __device__ unsigned int g_ctr;   // finish ticket
// legacy generic-A path state
static __device__ float g_cin[MAXC];
static __device__ unsigned int g_ctr2;

__device__ __forceinline__ float gamma8() {
    float g2 = GAMMA * GAMMA; float g4 = g2 * g2; return g4 * g4;
}

__device__ __forceinline__ void cp16(unsigned int saddr, const void* gptr) {
    asm volatile("cp.async.cg.shared.global [%0], [%1], 16;"
                 :: "r"(saddr), "l"(gptr) : "memory");
}
__device__ __forceinline__ void cp_commit() {
    asm volatile("cp.async.commit_group;" ::: "memory");
}
template <int N>
__device__ __forceinline__ void cp_wait() {
    asm volatile("cp.async.wait_group %0;" :: "n"(N) : "memory");
}

__device__ __forceinline__ void load8(const float* __restrict__ r, long long base,
                                      long long T, float rv[FPT]) {
    if (base + FPT <= T) {
        const float4* p = reinterpret_cast<const float4*>(r + base);
        float4 v0 = p[0], v1 = p[1];
        rv[0]=v0.x; rv[1]=v0.y; rv[2]=v0.z; rv[3]=v0.w;
        rv[4]=v1.x; rv[5]=v1.y; rv[6]=v1.z; rv[7]=v1.w;
    } else {
        #pragma unroll
        for (int j = 0; j < FPT; j++)
            rv[j] = (base + j < T) ? r[base + j] : 0.0f;
    }
}

// Warp inclusive suffix scan of affine (g,s): lane i -> aggregate [i..31].
__device__ __forceinline__ void warp_suffix_incl(float& g, float& s) {
    int lane = threadIdx.x & 31;
    #pragma unroll
    for (int off = 1; off < 32; off <<= 1) {
        float g2 = __shfl_down_sync(0xffffffffu, g, off);
        float s2 = __shfl_down_sync(0xffffffffu, s, off);
        if (lane + off < 32) { s = s + g * s2; g = g * g2; }
    }
}

// Block scan pieces: tval/tgain s.t. carry entering this thread's segment
// = tval + tgain * (carry entering the block). Leaves shg/shs = warp aggs.
__device__ __forceinline__ void thread_scan2(float gseg, float sseg,
                                             float* shg, float* shs,
                                             float& tval, float& tgain) {
    int lane = threadIdx.x & 31, wid = threadIdx.x >> 5;
    float g = gseg, s = sseg;
    warp_suffix_incl(g, s);
    float ge = __shfl_down_sync(0xffffffffu, g, 1);
    float se = __shfl_down_sync(0xffffffffu, s, 1);
    if (lane == 31) { ge = 1.0f; se = 0.0f; }
    if (lane == 0) { shg[wid] = g; shs[wid] = s; }
    __syncthreads();
    float gw = 1.0f, sw = 0.0f;
    for (int wv = wid + 1; wv < BT / 32; wv++) { sw = sw + gw * shs[wv]; gw = gw * shg[wv]; }
    tval = se + ge * sw;
    tgain = ge * gw;
}

// Legacy full thread_carry (generic path + k_agg tail)
__device__ __forceinline__ float thread_carry(float gseg, float sseg, float cin,
                                              float* shg, float* shs) {
    float tval, tgain;
    thread_scan2(gseg, sseg, shg, shs, tval, tgain);
    return tval + tgain * cin;
}

// Float warp reduce -> per-warp double partial -> warp0 double reduce -> atomics
__device__ __forceinline__ void block_reduce3f(float a, float b, float c) {
    #pragma unroll
    for (int o = 16; o > 0; o >>= 1) {
        a += __shfl_down_sync(0xffffffffu, a, o);
        b += __shfl_down_sync(0xffffffffu, b, o);
        c += __shfl_down_sync(0xffffffffu, c, o);
    }
    __shared__ double sa[8], sb[8], sc[8];
    int lane = threadIdx.x & 31, wid = threadIdx.x >> 5;
    if (lane == 0) { sa[wid] = (double)a; sb[wid] = (double)b; sc[wid] = (double)c; }
    __syncthreads();
    if (wid == 0) {
        int nw = blockDim.x >> 5;
        double da = (lane < nw) ? sa[lane] : 0.0;
        double db = (lane < nw) ? sb[lane] : 0.0;
        double dc = (lane < nw) ? sc[lane] : 0.0;
        #pragma unroll
        for (int o = 4; o > 0; o >>= 1) {
            da += __shfl_down_sync(0xffffffffu, da, o);
            db += __shfl_down_sync(0xffffffffu, db, o);
            dc += __shfl_down_sync(0xffffffffu, dc, o);
        }
        if (lane == 0) {
            atomicAdd(&g_acc[0], da);
            atomicAdd(&g_acc[1], db);
            atomicAdd(&g_acc[2], dc);
        }
    }
}

// ---------------------------------------------------------------------------
// Single fused kernel (A == 18). Block b handles chunk c = NC-1-b so the
// look-back only waits on earlier-scheduled blocks.
// ---------------------------------------------------------------------------
__global__ void __launch_bounds__(BT) k_one18(const float* __restrict__ w,
                                              const float* __restrict__ r,
                                              const int* __restrict__ as,
                                              long long T, int NC, float* out) {
    extern __shared__ __align__(16) char dyns[];
    char*  wbuf = dyns;                                            // NBUF*TBYTES
    float* sd   = reinterpret_cast<float*>(dyns + NBUF * TBYTES);  // FCHUNK
    __shared__ float shg[BT / 32], shs[BT / 32];
    __shared__ float sh_cin;
    __shared__ int slast;
    int tid = threadIdx.x;
    int lane = tid & 31, wid = tid >> 5;
    int c = NC - 1 - (int)blockIdx.x;                  // chunk id (reversed)
    long long cbase = (long long)c * FCHUNK;
    bool full = (cbase + FCHUNK <= T);
    const char* wg = reinterpret_cast<const char*>(w) + cbase * ROWB;

    unsigned int sb0 = (unsigned int)__cvta_generic_to_shared(wbuf);
    unsigned int sb1 = (unsigned int)__cvta_generic_to_shared(wbuf + TBYTES);

    // prologue: issue tile 0 immediately (overlaps scan + look-back)
    if (full) {
        #pragma unroll
        for (int i = tid; i < NG16; i += BT)
            cp16(sb0 + i * 16, wg + (long long)i * 16);
        cp_commit();
    }

    // --- local scan: thread aggregates + block scan pieces ---
    long long base = cbase + (long long)tid * FPT;
    float rv[FPT];
    load8(r, base, T, rv);
    int cnt = (int)max(0LL, min((long long)FPT, T - base));
    float carry = 0.0f;
    #pragma unroll
    for (int j = FPT - 1; j >= 0; --j) carry = carry * GAMMA + rv[j];
    float gseg = (cnt == FPT) ? gamma8() : __powf(GAMMA, (float)cnt);
    float tval, tgain;
    thread_scan2(gseg, carry, shg, shs, tval, tgain);

    // tid 0: block aggregate (G,S) from warp aggregates; publish AGG (or INC)
    float S = 0.0f, G = 1.0f;
    if (tid == 0) {
        #pragma unroll
        for (int wv = 0; wv < BT / 32; wv++) { S = S + G * shs[wv]; G = G * shg[wv]; }
        if (c == NC - 1) {
            *(volatile float*)&g_pi[c] = S;            // suffix carry beyond end = 0
            __threadfence();
            atomicExch(&g_st[c], 2);
        } else {
            *(volatile float*)&g_pg[c] = G;
            *(volatile float*)&g_ps[c] = S;
            __threadfence();
            atomicExch(&g_st[c], 1);
        }
    }

    // --- look-back (warp 0): carry entering this chunk from chunks c+1.. ---
    if (wid == 0) {
        float cin = 0.0f;
        if (c != NC - 1) {
            float accg = 1.0f, accs = 0.0f;
            int k = c + 1;
            bool done = false;
            while (!done) {
                int idx = k + lane;
                int f = 2;
                float vg = 1.0f, vs = 0.0f, vi = 0.0f;
                if (idx < NC) {
                    f = atomicAdd(&g_st[idx], 0);
                    while (f == 0) { __nanosleep(64); f = atomicAdd(&g_st[idx], 0); }
                }
                __threadfence();                       // acquire before value reads
                if (idx < NC) {
                    if (f == 2) vi = *(volatile float*)&g_pi[idx];
                    else { vg = *(volatile float*)&g_pg[idx]; vs = *(volatile float*)&g_ps[idx]; }
                }
                unsigned m = __ballot_sync(0xffffffffu, f == 2);
                int first = m ? (__ffs(m) - 1) : 32;
                for (int i = 0; i < first; i++) {      // fold nearest-first aggregates
                    float gg = __shfl_sync(0xffffffffu, vg, i);
                    float ss = __shfl_sync(0xffffffffu, vs, i);
                    accs += accg * ss; accg *= gg;
                }
                if (first < 32) {
                    float ii = __shfl_sync(0xffffffffu, vi, first);
                    cin = accs + accg * ii;
                    done = true;
                } else {
                    k += 32;
                }
            }
        }
        if (lane == 0) {
            sh_cin = cin;
            if (c != NC - 1) {                         // publish inclusive for readers
                *(volatile float*)&g_pi[c] = S + G * cin;
                __threadfence();
                atomicExch(&g_st[c], 2);
            }
        }
    }
    __syncthreads();
    float cin = sh_cin;

    // --- d replay into smem + partial sum(d) ---
    float tc = tval + tgain * cin;
    float dsum = 0.0f;
    {
        float c2 = tc;
        if (cnt == FPT) {
            float dloc[FPT];
            #pragma unroll
            for (int j = FPT - 1; j >= 0; --j) { c2 = c2 * GAMMA + rv[j]; dloc[j] = c2; }
            #pragma unroll
            for (int j = 0; j < FPT; j++) { sd[tid * FPT + j] = dloc[j]; dsum += dloc[j]; }
        } else {
            for (int j = FPT - 1; j >= 0; --j) {
                if (j < cnt) { c2 = c2 * GAMMA + rv[j]; sd[tid * FPT + j] = c2; dsum += c2; }
                else sd[tid * FPT + j] = 0.0f;
            }
        }
    }

    // issue tile 1 before entering mainloop
    if (full) {
        #pragma unroll
        for (int i = tid; i < NG16; i += BT)
            cp16(sb1 + i * 16, wg + (long long)TBYTES + (long long)i * 16);
        cp_commit();
    }
    __syncthreads();   // sd visible

    // --- mainloop: R12's proven 2-buffer ping-pong, one barrier per tile ---
    float pn = 0.0f, pp = 0.0f;
    if (full) {
        #pragma unroll
        for (int tile = 0; tile < NTILE; tile++) {
            if (tile + 1 < NTILE) cp_wait<1>(); else cp_wait<0>();
            __syncthreads();           // tile buffer visible; prev reads done

            if (tile + 1 < NTILE) {
                unsigned int dst = ((tile + 1) & 1) ? sb1 : sb0;
                const char* src = wg + (long long)(tile + 1) * TBYTES;
                #pragma unroll
                for (int i = tid; i < NG16; i += BT)
                    cp16(dst + i * 16, src + (long long)i * 16);
                cp_commit();
            }

            const float2* st = reinterpret_cast<const float2*>(wbuf + (tile & 1) * TBYTES);
            long long t = cbase + (long long)tile * BT + tid;
            int ai = as[t];
            const float2* myrow = st + tid * AH;
            float s0 = 0.0f, s1 = 0.0f;
            #pragma unroll
            for (int i = 0; i < AH; i++) {
                float2 v = myrow[i];
                s0 += __expf(v.x);
                s1 += __expf(v.y);
            }
            float2 va = myrow[ai >> 1];
            float wa = (ai & 1) ? va.y : va.x;
            float nll = __logf(s0 + s1) - wa;
            float d = sd[tile * BT + tid];
            pn += nll;
            pp += nll * d;
        }
        __syncthreads();
    } else {
        for (int tile = 0; tile < NTILE; tile++) {
            long long t = cbase + (long long)tile * BT + tid;
            if (t < T) {
                const float* row = w + (size_t)t * (AH * 2);
                const float2* p2 = reinterpret_cast<const float2*>(row);
                float s = 0.0f;
                #pragma unroll
                for (int i = 0; i < AH; i++) {
                    float2 v = __ldg(p2 + i);
                    s += __expf(v.x) + __expf(v.y);
                }
                int ai = as[t];
                float nll = __logf(s) - __ldg(row + ai);
                pn += nll;
                pp += nll * sd[tile * BT + tid];
            }
        }
        __syncthreads();
    }

    block_reduce3f(dsum, pn, pp);

    // finish ticket: last block finalizes and resets state for graph replay
    if (tid == 0) {
        __threadfence();
        slast = (atomicAdd(&g_ctr, 1u) == gridDim.x - 1u) ? 1 : 0;
    }
    __syncthreads();
    if (slast) {
        for (int i = tid; i < NC; i += BT) g_st[i] = 0;
        if (tid == 0) {
            __threadfence();
            double Td = (double)T;
            double ds = g_acc[0], ns = g_acc[1], ps = g_acc[2];
            out[0] = (float)((ps - ds * ns / Td) / Td);
            g_acc[0] = 0.0; g_acc[1] = 0.0; g_acc[2] = 0.0;
            g_ctr = 0u;
        }
    }
}

// ---------------------------------------------------------------------------
// Generic-A fallback (two launches, as R12)
// ---------------------------------------------------------------------------
__global__ void __launch_bounds__(BT) k_agg(const float* __restrict__ r, long long T) {
    __shared__ float shg[BT / 32], shs[BT / 32];
    __shared__ int is_last;
    int tid = threadIdx.x;
    int nchunk = gridDim.x;
    long long base = (long long)blockIdx.x * FCHUNK + (long long)tid * FPT;
    float rv[FPT];
    load8(r, base, T, rv);
    int cnt = (int)max(0LL, min((long long)FPT, T - base));
    float carry = 0.0f;
    #pragma unroll
    for (int j = FPT - 1; j >= 0; --j) carry = carry * GAMMA + rv[j];
    float gseg = (cnt == FPT) ? gamma8() : __powf(GAMMA, (float)cnt);
    (void)thread_carry(gseg, carry, 0.0f, shg, shs);
    __syncthreads();
    if (tid == 0) {
        float g = 1.0f, s = 0.0f;
        for (int wv = 0; wv < BT / 32; wv++) { s = s + g * shs[wv]; g = g * shg[wv]; }
        g_pg[blockIdx.x] = g; g_ps[blockIdx.x] = s;
        __threadfence();
        is_last = (atomicAdd(&g_ctr2, 1u) == (unsigned)nchunk - 1u) ? 1 : 0;
    }
    __syncthreads();
    if (!is_last) return;
    __threadfence();
    if (tid == 0) { g_acc[0] = 0.0; g_acc[1] = 0.0; g_acc[2] = 0.0;
                    g_ctr = 0u; g_ctr2 = 0u; }
    __syncthreads();
    int kc = (nchunk + BT - 1) / BT;
    int lo = tid * kc;
    int hi = min(lo + kc, nchunk);
    float cg = 1.0f, cs = 0.0f;
    for (int cc = lo; cc < hi; cc++) { cs = cs + cg * g_ps[cc]; cg = cg * g_pg[cc]; }
    float scarry = thread_carry(cg, cs, 0.0f, shg, shs);
    for (int cc = hi - 1; cc >= lo; --cc) {
        g_cin[cc] = scarry;
        scarry = g_ps[cc] + g_pg[cc] * scarry;
    }
}

__global__ void __launch_bounds__(BT) k_fused_gen(const float* __restrict__ w,
                                                  const float* __restrict__ r,
                                                  const int* __restrict__ as,
                                                  long long T, int A, float* out) {
    extern __shared__ __align__(16) char dyns[];
    float* sd = reinterpret_cast<float*>(dyns + NBUF * TBYTES);
    __shared__ float shg[BT / 32], shs[BT / 32];
    int tid = threadIdx.x;
    long long cbase = (long long)blockIdx.x * FCHUNK;
    long long base = cbase + (long long)tid * FPT;

    float rv[FPT];
    load8(r, base, T, rv);
    int cnt = (int)max(0LL, min((long long)FPT, T - base));
    float carry = 0.0f;
    #pragma unroll
    for (int j = FPT - 1; j >= 0; --j) carry = carry * GAMMA + rv[j];
    float gseg = (cnt == FPT) ? gamma8() : __powf(GAMMA, (float)cnt);
    float tc = thread_carry(gseg, carry, g_cin[blockIdx.x], shg, shs);

    float dsum = 0.0f;
    {
        float c2 = tc;
        for (int j = FPT - 1; j >= 0; --j) {
            if (j < cnt) { c2 = c2 * GAMMA + rv[j]; sd[tid * FPT + j] = c2; dsum += c2; }
            else sd[tid * FPT + j] = 0.0f;
        }
    }
    __syncthreads();

    float pn = 0.0f, pp = 0.0f;
    for (int j = 0; j < NTILE; j++) {
        long long t = cbase + (long long)j * BT + tid;
        if (t < T) {
            const float* row = w + (size_t)t * A;
            float m = __ldg(row);
            for (int i = 1; i < A; i++) m = fmaxf(m, __ldg(row + i));
            float s = 0.0f;
            for (int i = 0; i < A; i++) s += __expf(__ldg(row + i) - m);
            int ai = as[t];
            float nll = m + __logf(s) - __ldg(row + ai);
            pn += nll;
            pp += nll * sd[j * BT + tid];
        }
    }
    __syncthreads();
    block_reduce3f(dsum, pn, pp);

    if (tid == 0) {
        __threadfence();
        if (atomicAdd(&g_ctr, 1u) == gridDim.x - 1) {
            __threadfence();
            double Td = (double)T;
            double ds = g_acc[0], ns = g_acc[1], ps = g_acc[2];
            out[0] = (float)((ps - ds * ns / Td) / Td);
            g_acc[0] = 0.0; g_acc[1] = 0.0; g_acc[2] = 0.0;
            g_ctr = 0u;
        }
    }
}

extern "C" void kernel_launch(void* const* d_in, const int* in_sizes, int n_in,
                              void* d_out, int out_size) {
    const float* w  = (const float*)d_in[0];   // [T, A]
    const float* r  = (const float*)d_in[1];   // [T]
    const int*   as = (const int*)d_in[2];     // [T] int32
    long long T = (long long)in_sizes[1];
    int A = (int)((long long)in_sizes[0] / T);
    long long NCll = (T + FCHUNK - 1) / FCHUNK;
    if (NCll > MAXC) NCll = MAXC;
    int NC = (int)NCll;

    static int attr_done = 0;
    if (!attr_done) {
        cudaFuncSetAttribute(k_one18, cudaFuncAttributeMaxDynamicSharedMemorySize, DYNBYTES);
        cudaFuncSetAttribute(k_one18, cudaFuncAttributePreferredSharedMemoryCarveout, 100);
        cudaFuncSetAttribute(k_fused_gen, cudaFuncAttributeMaxDynamicSharedMemorySize, DYNBYTES);
        attr_done = 1;
    }

    if (A == 18) {
        k_one18<<<NC, BT, DYNBYTES>>>(w, r, as, T, NC, (float*)d_out);
    } else {
        k_agg<<<NC, BT>>>(r, T);
        k_fused_gen<<<NC, BT, DYNBYTES>>>(w, r, as, T, A, (float*)d_out);
    }
}

// round 17
// speedup vs baseline: 1.8831x; 1.6818x over previous
#include <cuda_runtime.h>
#include <cstdint>
#include <math.h>

// ---------------------------------------------------------------------------
// PolicyGradientLoss: out = mean( nll(w,a) * (D - mean D) )
//   D[t] = sum_{k>=t} gamma^{k-t} r[k]
//   nll[t] = logsumexp(w[t,:]) - w[t, a[t]]
// Identity: mean(nll*(D-mD)) = (S_pd - S_d*S_n/T)/T
// ep_as is int32 on device.
//
// R17 (= R16 + exp2f fix): single kernel, NO global scan. gamma^2048 ~ 1.1e-9,
// so each block's scan carry is computed locally from the NEXT 2048 r values
// (truncation error ~1e-9 rel, vastly below the 1e-3 gate). Mainloop = R12's
// proven 2-buffer cp.async ping-pong, one barrier per tile. Last-block ticket
// finalizes and resets for graph replay.
// ---------------------------------------------------------------------------

#define GAMMA 0.99f
#define LOG2_G8 (-0.11599655f)          // 8 * log2(0.99)
#define BT 256                          // threads per block (8 warps)
#define FPT 8                           // rows per thread in scan
#define FCHUNK (BT * FPT)               // 2048 rows per block
#define MAXT (1 << 22)
#define MAXC (MAXT / FCHUNK)
#define AH 9                            // float2 per row (A = 18)
#define ROWB 72                         // bytes per row
#define TBYTES (BT * ROWB)              // 18432 B per 256-row tile
#define NG16 (TBYTES / 16)              // 1152 granules per tile
#define NBUF 2
#define NTILE (FCHUNK / BT)             // 8 tiles per chunk
#define DYNBYTES (NBUF * TBYTES + FCHUNK * 4)   // 45056

static __device__ double g_acc[3];      // [0]=sum d, [1]=sum nll, [2]=sum nll*d
static __device__ unsigned int g_ctr;   // finish ticket
// generic-A fallback state
static __device__ float g_cg[MAXC];
static __device__ float g_cs[MAXC];
static __device__ float g_cin[MAXC];
static __device__ unsigned int g_ctr2;

__device__ __forceinline__ float gamma8() {
    float g2 = GAMMA * GAMMA; float g4 = g2 * g2; return g4 * g4;
}

__device__ __forceinline__ void cp16(unsigned int saddr, const void* gptr) {
    asm volatile("cp.async.cg.shared.global [%0], [%1], 16;"
                 :: "r"(saddr), "l"(gptr) : "memory");
}
__device__ __forceinline__ void cp_commit() {
    asm volatile("cp.async.commit_group;" ::: "memory");
}
template <int N>
__device__ __forceinline__ void cp_wait() {
    asm volatile("cp.async.wait_group %0;" :: "n"(N) : "memory");
}

__device__ __forceinline__ void load8(const float* __restrict__ r, long long base,
                                      long long T, float rv[FPT]) {
    if (base + FPT <= T) {
        const float4* p = reinterpret_cast<const float4*>(r + base);
        float4 v0 = p[0], v1 = p[1];
        rv[0]=v0.x; rv[1]=v0.y; rv[2]=v0.z; rv[3]=v0.w;
        rv[4]=v1.x; rv[5]=v1.y; rv[6]=v1.z; rv[7]=v1.w;
    } else {
        #pragma unroll
        for (int j = 0; j < FPT; j++)
            rv[j] = (base + j < T) ? r[base + j] : 0.0f;
    }
}

// Warp inclusive suffix scan of affine (g,s): lane i -> aggregate [i..31].
__device__ __forceinline__ void warp_suffix_incl(float& g, float& s) {
    int lane = threadIdx.x & 31;
    #pragma unroll
    for (int off = 1; off < 32; off <<= 1) {
        float g2 = __shfl_down_sync(0xffffffffu, g, off);
        float s2 = __shfl_down_sync(0xffffffffu, s, off);
        if (lane + off < 32) { s = s + g * s2; g = g * g2; }
    }
}

// Carry entering this thread's segment given block-incoming carry cin.
// Leaves shg/shs = warp aggregates (callers must sync before reusing them).
__device__ __forceinline__ float thread_carry(float gseg, float sseg, float cin,
                                              float* shg, float* shs) {
    int lane = threadIdx.x & 31, wid = threadIdx.x >> 5;
    float g = gseg, s = sseg;
    warp_suffix_incl(g, s);
    float ge = __shfl_down_sync(0xffffffffu, g, 1);
    float se = __shfl_down_sync(0xffffffffu, s, 1);
    if (lane == 31) { ge = 1.0f; se = 0.0f; }
    if (lane == 0) { shg[wid] = g; shs[wid] = s; }
    __syncthreads();
    float gw = 1.0f, sw = 0.0f;
    for (int wv = wid + 1; wv < BT / 32; wv++) { sw = sw + gw * shs[wv]; gw = gw * shg[wv]; }
    return se + ge * (sw + gw * cin);
}

// Float warp reduce -> per-warp double partial -> warp0 double reduce -> atomics
__device__ __forceinline__ void block_reduce3f(float a, float b, float c) {
    #pragma unroll
    for (int o = 16; o > 0; o >>= 1) {
        a += __shfl_down_sync(0xffffffffu, a, o);
        b += __shfl_down_sync(0xffffffffu, b, o);
        c += __shfl_down_sync(0xffffffffu, c, o);
    }
    __shared__ double sa[8], sb[8], sc[8];
    int lane = threadIdx.x & 31, wid = threadIdx.x >> 5;
    if (lane == 0) { sa[wid] = (double)a; sb[wid] = (double)b; sc[wid] = (double)c; }
    __syncthreads();
    if (wid == 0) {
        int nw = blockDim.x >> 5;
        double da = (lane < nw) ? sa[lane] : 0.0;
        double db = (lane < nw) ? sb[lane] : 0.0;
        double dc = (lane < nw) ? sc[lane] : 0.0;
        #pragma unroll
        for (int o = 4; o > 0; o >>= 1) {
            da += __shfl_down_sync(0xffffffffu, da, o);
            db += __shfl_down_sync(0xffffffffu, db, o);
            dc += __shfl_down_sync(0xffffffffu, dc, o);
        }
        if (lane == 0) {
            atomicAdd(&g_acc[0], da);
            atomicAdd(&g_acc[1], db);
            atomicAdd(&g_acc[2], dc);
        }
    }
}

// ---------------------------------------------------------------------------
// Single fused kernel (A == 18), fully parallel blocks.
// ---------------------------------------------------------------------------
__global__ void __launch_bounds__(BT) k_one18(const float* __restrict__ w,
                                              const float* __restrict__ r,
                                              const int* __restrict__ as,
                                              long long T, float* out) {
    extern __shared__ __align__(16) char dyns[];
    char*  wbuf = dyns;                                            // NBUF*TBYTES
    float* sd   = reinterpret_cast<float*>(dyns + NBUF * TBYTES);  // FCHUNK
    __shared__ float shg[BT / 32], shs[BT / 32];
    __shared__ float sh_cin;
    __shared__ int slast;
    int tid = threadIdx.x;
    int lane = tid & 31, wid = tid >> 5;
    long long cbase = (long long)blockIdx.x * FCHUNK;
    bool full = (cbase + FCHUNK <= T);
    const char* wg = reinterpret_cast<const char*>(w) + cbase * ROWB;

    unsigned int sb0 = (unsigned int)__cvta_generic_to_shared(wbuf);
    unsigned int sb1 = (unsigned int)__cvta_generic_to_shared(wbuf + TBYTES);

    // prologue: issue tile 0 immediately (overlaps everything below)
    if (full) {
        #pragma unroll
        for (int i = tid; i < NG16; i += BT)
            cp16(sb0 + i * 16, wg + (long long)i * 16);
        cp_commit();
    }

    // --- load own r segment and the lookahead segment ---
    long long base = cbase + (long long)tid * FPT;
    float rv[FPT], rn[FPT];
    load8(r, base, T, rv);
    load8(r, base + FCHUNK, T, rn);    // next chunk (zeros past T)

    // --- local carry-in from the next 2048 r values (gamma-truncated) ---
    // cin = sum_t (g8^t) * Horner(rn_t);  g8^t via exp2f(t * 8*log2(gamma))
    {
        float v = 0.0f;
        #pragma unroll
        for (int j = FPT - 1; j >= 0; --j) v = v * GAMMA + rn[j];
        float wgt = exp2f((float)tid * LOG2_G8);
        float x = v * wgt;
        #pragma unroll
        for (int o = 16; o > 0; o >>= 1) x += __shfl_down_sync(0xffffffffu, x, o);
        if (lane == 0) shs[wid] = x;
        __syncthreads();
        if (tid == 0) {
            float c = 0.0f;
            #pragma unroll
            for (int wv = 0; wv < BT / 32; wv++) c += shs[wv];
            sh_cin = c;
        }
        __syncthreads();
    }
    float cin = sh_cin;
    __syncthreads();                   // everyone has cin; shs reusable

    // --- block scan of own segment with carry-in ---
    int cnt = (int)max(0LL, min((long long)FPT, T - base));
    float carry = 0.0f;
    #pragma unroll
    for (int j = FPT - 1; j >= 0; --j) carry = carry * GAMMA + rv[j];
    float gseg = (cnt == FPT) ? gamma8() : __powf(GAMMA, (float)cnt);
    float tc = thread_carry(gseg, carry, cin, shg, shs);

    float dsum = 0.0f;
    {
        float c2 = tc;
        if (cnt == FPT) {
            float dloc[FPT];
            #pragma unroll
            for (int j = FPT - 1; j >= 0; --j) { c2 = c2 * GAMMA + rv[j]; dloc[j] = c2; }
            #pragma unroll
            for (int j = 0; j < FPT; j++) { sd[tid * FPT + j] = dloc[j]; dsum += dloc[j]; }
        } else {
            for (int j = FPT - 1; j >= 0; --j) {
                if (j < cnt) { c2 = c2 * GAMMA + rv[j]; sd[tid * FPT + j] = c2; dsum += c2; }
                else sd[tid * FPT + j] = 0.0f;
            }
        }
    }

    // issue tile 1 before mainloop
    if (full) {
        #pragma unroll
        for (int i = tid; i < NG16; i += BT)
            cp16(sb1 + i * 16, wg + (long long)TBYTES + (long long)i * 16);
        cp_commit();
    }
    __syncthreads();   // sd visible block-wide

    // --- mainloop: R12's proven 2-buffer ping-pong, one barrier per tile ---
    float pn = 0.0f, pp = 0.0f;
    if (full) {
        #pragma unroll
        for (int tile = 0; tile < NTILE; tile++) {
            if (tile + 1 < NTILE) cp_wait<1>(); else cp_wait<0>();
            __syncthreads();           // tile buffer visible; prev reads done

            if (tile + 1 < NTILE) {
                unsigned int dst = ((tile + 1) & 1) ? sb1 : sb0;
                const char* src = wg + (long long)(tile + 1) * TBYTES;
                #pragma unroll
                for (int i = tid; i < NG16; i += BT)
                    cp16(dst + i * 16, src + (long long)i * 16);
                cp_commit();
            }

            const float2* st = reinterpret_cast<const float2*>(wbuf + (tile & 1) * TBYTES);
            long long t = cbase + (long long)tile * BT + tid;
            int ai = as[t];
            const float2* myrow = st + tid * AH;
            float s0 = 0.0f, s1 = 0.0f;
            #pragma unroll
            for (int i = 0; i < AH; i++) {
                float2 v = myrow[i];
                s0 += __expf(v.x);
                s1 += __expf(v.y);
            }
            float2 va = myrow[ai >> 1];
            float wa = (ai & 1) ? va.y : va.x;
            float nll = __logf(s0 + s1) - wa;
            float d = sd[tile * BT + tid];
            pn += nll;
            pp += nll * d;
        }
        __syncthreads();
    } else {
        for (int tile = 0; tile < NTILE; tile++) {
            long long t = cbase + (long long)tile * BT + tid;
            if (t < T) {
                const float* row = w + (size_t)t * (AH * 2);
                const float2* p2 = reinterpret_cast<const float2*>(row);
                float s = 0.0f;
                #pragma unroll
                for (int i = 0; i < AH; i++) {
                    float2 v = __ldg(p2 + i);
                    s += __expf(v.x) + __expf(v.y);
                }
                int ai = as[t];
                float nll = __logf(s) - __ldg(row + ai);
                pn += nll;
                pp += nll * sd[tile * BT + tid];
            }
        }
        __syncthreads();
    }

    block_reduce3f(dsum, pn, pp);

    // finish ticket: last block finalizes and resets state for graph replay
    if (tid == 0) {
        __threadfence();
        slast = (atomicAdd(&g_ctr, 1u) == gridDim.x - 1u) ? 1 : 0;
    }
    __syncthreads();
    if (slast && tid == 0) {
        __threadfence();
        double Td = (double)T;
        double ds = g_acc[0], ns = g_acc[1], ps = g_acc[2];
        out[0] = (float)((ps - ds * ns / Td) / Td);
        g_acc[0] = 0.0; g_acc[1] = 0.0; g_acc[2] = 0.0;
        g_ctr = 0u;
    }
}

// ---------------------------------------------------------------------------
// Generic-A fallback (two launches, R12 structure)
// ---------------------------------------------------------------------------
__global__ void __launch_bounds__(BT) k_agg(const float* __restrict__ r, long long T) {
    __shared__ float shg[BT / 32], shs[BT / 32];
    __shared__ int is_last;
    int tid = threadIdx.x;
    int nchunk = gridDim.x;
    long long base = (long long)blockIdx.x * FCHUNK + (long long)tid * FPT;
    float rv[FPT];
    load8(r, base, T, rv);
    int cnt = (int)max(0LL, min((long long)FPT, T - base));
    float carry = 0.0f;
    #pragma unroll
    for (int j = FPT - 1; j >= 0; --j) carry = carry * GAMMA + rv[j];
    float gseg = (cnt == FPT) ? gamma8() : __powf(GAMMA, (float)cnt);
    (void)thread_carry(gseg, carry, 0.0f, shg, shs);
    __syncthreads();
    if (tid == 0) {
        float g = 1.0f, s = 0.0f;
        for (int wv = 0; wv < BT / 32; wv++) { s = s + g * shs[wv]; g = g * shg[wv]; }
        g_cg[blockIdx.x] = g; g_cs[blockIdx.x] = s;
        __threadfence();
        is_last = (atomicAdd(&g_ctr2, 1u) == (unsigned)nchunk - 1u) ? 1 : 0;
    }
    __syncthreads();
    if (!is_last) return;
    __threadfence();
    if (tid == 0) { g_acc[0] = 0.0; g_acc[1] = 0.0; g_acc[2] = 0.0;
                    g_ctr = 0u; g_ctr2 = 0u; }
    __syncthreads();
    int kc = (nchunk + BT - 1) / BT;
    int lo = tid * kc;
    int hi = min(lo + kc, nchunk);
    float cg = 1.0f, cs = 0.0f;
    for (int cc = lo; cc < hi; cc++) { cs = cs + cg * g_cs[cc]; cg = cg * g_cg[cc]; }
    float scarry = thread_carry(cg, cs, 0.0f, shg, shs);
    for (int cc = hi - 1; cc >= lo; --cc) {
        g_cin[cc] = scarry;
        scarry = g_cs[cc] + g_cg[cc] * scarry;
    }
}

__global__ void __launch_bounds__(BT) k_fused_gen(const float* __restrict__ w,
                                                  const float* __restrict__ r,
                                                  const int* __restrict__ as,
                                                  long long T, int A, float* out) {
    extern __shared__ __align__(16) char dyns[];
    float* sd = reinterpret_cast<float*>(dyns + NBUF * TBYTES);
    __shared__ float shg[BT / 32], shs[BT / 32];
    int tid = threadIdx.x;
    long long cbase = (long long)blockIdx.x * FCHUNK;
    long long base = cbase + (long long)tid * FPT;

    float rv[FPT];
    load8(r, base, T, rv);
    int cnt = (int)max(0LL, min((long long)FPT, T - base));
    float carry = 0.0f;
    #pragma unroll
    for (int j = FPT - 1; j >= 0; --j) carry = carry * GAMMA + rv[j];
    float gseg = (cnt == FPT) ? gamma8() : __powf(GAMMA, (float)cnt);
    float tc = thread_carry(gseg, carry, g_cin[blockIdx.x], shg, shs);

    float dsum = 0.0f;
    {
        float c2 = tc;
        for (int j = FPT - 1; j >= 0; --j) {
            if (j < cnt) { c2 = c2 * GAMMA + rv[j]; sd[tid * FPT + j] = c2; dsum += c2; }
            else sd[tid * FPT + j] = 0.0f;
        }
    }
    __syncthreads();

    float pn = 0.0f, pp = 0.0f;
    for (int j = 0; j < NTILE; j++) {
        long long t = cbase + (long long)j * BT + tid;
        if (t < T) {
            const float* row = w + (size_t)t * A;
            float m = __ldg(row);
            for (int i = 1; i < A; i++) m = fmaxf(m, __ldg(row + i));
            float s = 0.0f;
            for (int i = 0; i < A; i++) s += __expf(__ldg(row + i) - m);
            int ai = as[t];
            float nll = m + __logf(s) - __ldg(row + ai);
            pn += nll;
            pp += nll * sd[j * BT + tid];
        }
    }
    __syncthreads();
    block_reduce3f(dsum, pn, pp);

    if (tid == 0) {
        __threadfence();
        if (atomicAdd(&g_ctr, 1u) == gridDim.x - 1) {
            __threadfence();
            double Td = (double)T;
            double ds = g_acc[0], ns = g_acc[1], ps = g_acc[2];
            out[0] = (float)((ps - ds * ns / Td) / Td);
            g_acc[0] = 0.0; g_acc[1] = 0.0; g_acc[2] = 0.0;
            g_ctr = 0u;
        }
    }
}

extern "C" void kernel_launch(void* const* d_in, const int* in_sizes, int n_in,
                              void* d_out, int out_size) {
    const float* w  = (const float*)d_in[0];   // [T, A]
    const float* r  = (const float*)d_in[1];   // [T]
    const int*   as = (const int*)d_in[2];     // [T] int32
    long long T = (long long)in_sizes[1];
    int A = (int)((long long)in_sizes[0] / T);
    long long NCll = (T + FCHUNK - 1) / FCHUNK;
    if (NCll > MAXC) NCll = MAXC;
    int NC = (int)NCll;

    static int attr_done = 0;
    if (!attr_done) {
        cudaFuncSetAttribute(k_one18, cudaFuncAttributeMaxDynamicSharedMemorySize, DYNBYTES);
        cudaFuncSetAttribute(k_one18, cudaFuncAttributePreferredSharedMemoryCarveout, 100);
        cudaFuncSetAttribute(k_fused_gen, cudaFuncAttributeMaxDynamicSharedMemorySize, DYNBYTES);
        attr_done = 1;
    }

    if (A == 18) {
        k_one18<<<NC, BT, DYNBYTES>>>(w, r, as, T, (float*)d_out);
    } else {
        k_agg<<<NC, BT>>>(r, T);
        k_fused_gen<<<NC, BT, DYNBYTES>>>(w, r, as, T, A, (float*)d_out);
    }
}